// round 3
// baseline (speedup 1.0000x reference)
#include <cuda_runtime.h>

// Problem constants (fixed by the reference)
#define BB 4
#define SS 2048
#define DD 2048
#define N1 160                 // LoRA rank total (5 modes x 32)
#define MT (BB * SS)           // 8192 rows (tokens)
#define SROWS 66               // (2 + HEAD_SIZE) state rows per batch
#define OUT_X_ELEMS (MT * 5 * DD)

// Scratch: H[b*S+s][160] = tanh((x + sx*tmx) @ W1)
__device__ float g_H[(size_t)MT * N1];

// ---------------------------------------------------------------------------
// Kernel 1: token-shift mix + GEMM1 (D=2048 -> 160) + tanh
// Block: 64 rows x 160 cols, 256 threads, thread tile 8x5.
// ---------------------------------------------------------------------------
__global__ __launch_bounds__(256) void k1_mix_gemm1(
    const float* __restrict__ x,
    const float* __restrict__ state,
    const float* __restrict__ tmx,
    const float* __restrict__ w1,
    const int* __restrict__ ip)
{
    const int i1 = 66 * ip[0] + 1;

    __shared__ float As[16][65];    // [k][m], padded (conflict-free stores)
    __shared__ float Bs[16][160];   // [k][n]

    const int tid = threadIdx.x;
    const int m0  = blockIdx.x * 64;

    // A-tile load mapping: each thread loads 4 consecutive k for one row
    const int lrow = tid >> 2;          // 0..63
    const int lk   = (tid & 3) * 4;     // 0,4,8,12
    const int r    = m0 + lrow;
    const int t    = r & (SS - 1);
    const int b    = r >> 11;
    const float* xrow = x + (size_t)r * DD;
    const float* prow = (t > 0)
        ? (x + (size_t)(r - 1) * DD)
        : (state + ((size_t)b * SROWS + (size_t)i1) * DD);

    // compute mapping
    const int ty = tid >> 5;   // 0..7  -> rows ty*8 + ii
    const int tx = tid & 31;   // cols tx + 32*j

    float acc[8][5];
    #pragma unroll
    for (int ii = 0; ii < 8; ii++)
        #pragma unroll
        for (int j = 0; j < 5; j++) acc[ii][j] = 0.f;

    for (int kt = 0; kt < DD; kt += 16) {
        // load A tile (compute xmix on the fly)
        float4 xv = *(const float4*)(xrow + kt + lk);
        float4 pv = *(const float4*)(prow + kt + lk);
        float4 tv = *(const float4*)(tmx  + kt + lk);
        As[lk + 0][lrow] = xv.x + (pv.x - xv.x) * tv.x;
        As[lk + 1][lrow] = xv.y + (pv.y - xv.y) * tv.y;
        As[lk + 2][lrow] = xv.z + (pv.z - xv.z) * tv.z;
        As[lk + 3][lrow] = xv.w + (pv.w - xv.w) * tv.w;

        // load B tile: 16 x 160 = 2560 floats, 10 per thread, coalesced
        #pragma unroll
        for (int jj = 0; jj < 10; jj++) {
            int idx = tid + jj * 256;
            int kk = idx / 160;
            int nn = idx - kk * 160;
            Bs[kk][nn] = w1[(size_t)(kt + kk) * N1 + nn];
        }
        __syncthreads();

        #pragma unroll
        for (int k = 0; k < 16; k++) {
            float a[8], bv[5];
            #pragma unroll
            for (int ii = 0; ii < 8; ii++) a[ii] = As[k][ty * 8 + ii];
            #pragma unroll
            for (int j = 0; j < 5; j++) bv[j] = Bs[k][tx + 32 * j];
            #pragma unroll
            for (int ii = 0; ii < 8; ii++)
                #pragma unroll
                for (int j = 0; j < 5; j++)
                    acc[ii][j] = fmaf(a[ii], bv[j], acc[ii][j]);
        }
        __syncthreads();
    }

    #pragma unroll
    for (int ii = 0; ii < 8; ii++) {
        const size_t rr = (size_t)(m0 + ty * 8 + ii) * N1;
        #pragma unroll
        for (int j = 0; j < 5; j++)
            g_H[rr + tx + 32 * j] = tanhf(acc[ii][j]);
    }
}

// ---------------------------------------------------------------------------
// Kernel 2: 5x GEMM2 (32 -> 2048) fused with epilogue
//   out[r][f][d] = x[r][d] + sx[r][d] * (maa_f[d] + sum_k H[r][f*32+k]*W2[f][k][d])
// Block: 64 rows x 64 d-cols x 5 modes. 256 threads: 16 d-quads x 16 row-groups(x4).
// ---------------------------------------------------------------------------
__global__ __launch_bounds__(256) void k2_gemm2_epilogue(
    const float* __restrict__ x,
    const float* __restrict__ state,
    const float* __restrict__ w2,
    const float* __restrict__ mk,
    const float* __restrict__ mw,
    const float* __restrict__ mv,
    const float* __restrict__ mr,
    const float* __restrict__ mg,
    const int* __restrict__ ip,
    float* __restrict__ out)
{
    const int i1 = 66 * ip[0] + 1;

    __shared__ float W2s[160][64];  // [f*32+k][d-local], 40 KB

    const int tid = threadIdx.x;
    const int d0  = blockIdx.x * 64;
    const int r0  = blockIdx.y * 64;

    // load W2 tile: 160 rows x 64 cols, 16 float4-lanes per row
    {
        const int col4 = (tid & 15) * 4;      // 0..60 step 4
        const int rowb = tid >> 4;            // 0..15
        #pragma unroll
        for (int p = 0; p < 10; p++) {
            int c = rowb + p * 16;            // 0..159
            float4 v = *(const float4*)(w2 + (size_t)c * DD + d0 + col4);
            *(float4*)(&W2s[c][col4]) = v;
        }
    }
    __syncthreads();

    const int dq = tid & 15;        // d-quad: local d = dq*4 .. dq*4+3
    const int rg = tid >> 4;        // row group: rows rg*4 .. rg*4+3 (local)

    const float* hbase[4];
    #pragma unroll
    for (int rr = 0; rr < 4; rr++)
        hbase[rr] = g_H + (size_t)(r0 + rg * 4 + rr) * N1;

    float4 acc[4][5];
    #pragma unroll
    for (int rr = 0; rr < 4; rr++)
        #pragma unroll
        for (int f = 0; f < 5; f++) acc[rr][f] = make_float4(0.f, 0.f, 0.f, 0.f);

    #pragma unroll
    for (int f = 0; f < 5; f++) {
        #pragma unroll 8
        for (int k = 0; k < 32; k++) {
            const int c = f * 32 + k;
            float4 wv = *(const float4*)(&W2s[c][dq * 4]);
            #pragma unroll
            for (int rr = 0; rr < 4; rr++) {
                float h = __ldg(hbase[rr] + c);
                acc[rr][f].x = fmaf(wv.x, h, acc[rr][f].x);
                acc[rr][f].y = fmaf(wv.y, h, acc[rr][f].y);
                acc[rr][f].z = fmaf(wv.z, h, acc[rr][f].z);
                acc[rr][f].w = fmaf(wv.w, h, acc[rr][f].w);
            }
        }
    }

    const float* maa[5] = {mk, mw, mv, mr, mg};
    const int d = d0 + dq * 4;

    #pragma unroll
    for (int rr = 0; rr < 4; rr++) {
        const int r = r0 + rg * 4 + rr;
        const int t = r & (SS - 1);
        const int b = r >> 11;
        float4 xv = *(const float4*)(x + (size_t)r * DD + d);
        float4 pv;
        if (t > 0) pv = *(const float4*)(x + (size_t)(r - 1) * DD + d);
        else       pv = *(const float4*)(state + ((size_t)b * SROWS + (size_t)i1) * DD + d);
        float4 sx = make_float4(pv.x - xv.x, pv.y - xv.y, pv.z - xv.z, pv.w - xv.w);

        #pragma unroll
        for (int f = 0; f < 5; f++) {
            float4 mv4 = *(const float4*)(maa[f] + d);
            float4 o;
            o.x = fmaf(sx.x, mv4.x + acc[rr][f].x, xv.x);
            o.y = fmaf(sx.y, mv4.y + acc[rr][f].y, xv.y);
            o.z = fmaf(sx.z, mv4.z + acc[rr][f].z, xv.z);
            o.w = fmaf(sx.w, mv4.w + acc[rr][f].w, xv.w);
            *(float4*)(out + ((size_t)r * 5 + f) * DD + d) = o;
        }
    }
}

// ---------------------------------------------------------------------------
// Kernel 3: new_state = state with row i1 <- x[:, S-1]
// ---------------------------------------------------------------------------
__global__ __launch_bounds__(256) void k3_state(
    const float* __restrict__ x,
    const float* __restrict__ state,
    const int* __restrict__ ip,
    float* __restrict__ out_state)
{
    const int i1 = 66 * ip[0] + 1;
    int idx = blockIdx.x * blockDim.x + threadIdx.x;
    const int total = BB * SROWS * DD;
    if (idx >= total) return;
    int d    = idx & (DD - 1);
    int rowg = idx >> 11;          // b*66 + row
    int row  = rowg % SROWS;
    int b    = rowg / SROWS;
    float v = (row == i1)
        ? x[((size_t)b * SS + (SS - 1)) * DD + d]
        : state[idx];
    out_state[idx] = v;
}

// ---------------------------------------------------------------------------
extern "C" void kernel_launch(void* const* d_in, const int* in_sizes, int n_in,
                              void* d_out, int out_size)
{
    const float* x     = (const float*)d_in[0];
    const float* state = (const float*)d_in[1];
    const float* tmx   = (const float*)d_in[2];
    const float* w1    = (const float*)d_in[3];
    const float* w2    = (const float*)d_in[4];
    const float* mk    = (const float*)d_in[5];
    const float* mw    = (const float*)d_in[6];
    const float* mv    = (const float*)d_in[7];
    const float* mr    = (const float*)d_in[8];
    const float* mg    = (const float*)d_in[9];
    const int*   ip    = (const int*)d_in[10];

    float* out = (float*)d_out;

    k1_mix_gemm1<<<MT / 64, 256>>>(x, state, tmx, w1, ip);

    dim3 g2(DD / 64, MT / 64);
    k2_gemm2_epilogue<<<g2, 256>>>(x, state, w2, mk, mw, mv, mr, mg, ip, out);

    const int stotal = BB * SROWS * DD;
    k3_state<<<(stotal + 255) / 256, 256>>>(x, state, ip, out + OUT_X_ELEMS);
}

// round 4
// speedup vs baseline: 2.1828x; 2.1828x over previous
#include <cuda_runtime.h>
#include <cstdint>

// Problem constants (fixed by the reference)
#define BB 4
#define SS 2048
#define DD 2048
#define N1 160                 // LoRA rank total (5 modes x 32)
#define MT (BB * SS)           // 8192 rows (tokens)
#define SROWS 66               // (2 + HEAD_SIZE) state rows per batch
#define OUT_X_ELEMS ((size_t)MT * 5 * DD)

// Scratch: H[r][160] = tanh((x + sx*tmx) @ W1), stored tf32-rounded
__device__ float g_H[(size_t)MT * N1];

// ---------------------------------------------------------------------------
// tf32 helpers
// ---------------------------------------------------------------------------
__device__ __forceinline__ float to_tf32(float x) {
    float r;
    asm("cvt.rna.tf32.f32 %0, %1;" : "=f"(r) : "f"(x));
    return r;
}

__device__ __forceinline__ void mma_tf32(float c[4], const unsigned a[4],
                                         unsigned b0, unsigned b1) {
    asm volatile(
        "mma.sync.aligned.m16n8k8.row.col.f32.tf32.tf32.f32 "
        "{%0,%1,%2,%3}, {%4,%5,%6,%7}, {%8,%9}, {%0,%1,%2,%3};"
        : "+f"(c[0]), "+f"(c[1]), "+f"(c[2]), "+f"(c[3])
        : "r"(a[0]), "r"(a[1]), "r"(a[2]), "r"(a[3]), "r"(b0), "r"(b1));
}

// ---------------------------------------------------------------------------
// Kernel 1: token-shift mix + GEMM1 (8192x2048 @ 2048x160) + tanh, tf32 MMA.
// Block: M=64, N=160, BK=32. 256 threads = 8 warps, warp-tile m32 x n40.
// Register-staged software pipeline over the K loop.
// ---------------------------------------------------------------------------
__global__ __launch_bounds__(256) void k1_mix_gemm1(
    const float* __restrict__ x,
    const float* __restrict__ state,
    const float* __restrict__ tmx,
    const float* __restrict__ w1,
    const int* __restrict__ ip)
{
    const int i1 = SROWS * ip[0] + 1;

    __shared__ float As[64][36];     // xmix tile, tf32 bits, [m][k] (pad 36: conflict-free frags)
    __shared__ float Ws[32][168];    // W1 tile, tf32 bits, [k][n] (pad 168: (8k+n)%32 distinct)

    const int tid  = threadIdx.x;
    const int lane = tid & 31;
    const int warp = tid >> 5;
    const int wm   = warp & 1;       // m-super: rows wm*32
    const int wn   = warp >> 1;      // n-group: cols wn*40 (5 n8-tiles)
    const int m0   = blockIdx.x * 64;

    // ---- A-loader mapping: 2 float4 per thread (64 rows x 32 k) ----
    const float* xp[2]; const float* pp[2];
    int kq[2], arow[2];
    #pragma unroll
    for (int j = 0; j < 2; j++) {
        int idx = tid + j * 256;
        arow[j] = idx >> 3;              // 0..63
        kq[j]   = (idx & 7) * 4;         // 0..28
        int r = m0 + arow[j];
        xp[j] = x + (size_t)r * DD;
        int t = r & (SS - 1);
        pp[j] = (t > 0) ? x + (size_t)(r - 1) * DD
                        : state + ((size_t)(r >> 11) * SROWS + (size_t)i1) * DD;
    }
    // ---- W-loader mapping: 5 float4 per thread (32 rows x 160 n) ----
    int wrow[5], wc4[5];
    #pragma unroll
    for (int j = 0; j < 5; j++) {
        int idx = tid + j * 256;
        wrow[j] = idx / 40;              // 0..31
        wc4[j]  = (idx % 40) * 4;        // 0..156
    }

    float4 aS[2], wS[5];
    // prologue: stage kt = 0
    #pragma unroll
    for (int j = 0; j < 2; j++) {
        float4 xv = *(const float4*)(xp[j] + kq[j]);
        float4 pv = *(const float4*)(pp[j] + kq[j]);
        float4 tv = *(const float4*)(tmx + kq[j]);
        aS[j].x = xv.x + (pv.x - xv.x) * tv.x;
        aS[j].y = xv.y + (pv.y - xv.y) * tv.y;
        aS[j].z = xv.z + (pv.z - xv.z) * tv.z;
        aS[j].w = xv.w + (pv.w - xv.w) * tv.w;
    }
    #pragma unroll
    for (int j = 0; j < 5; j++)
        wS[j] = *(const float4*)(w1 + (size_t)wrow[j] * N1 + wc4[j]);

    float acc[2][5][4];
    #pragma unroll
    for (int h = 0; h < 2; h++)
        #pragma unroll
        for (int t = 0; t < 5; t++)
            #pragma unroll
            for (int q = 0; q < 4; q++) acc[h][t][q] = 0.f;

    for (int kt = 0; kt < DD; kt += 32) {
        __syncthreads();   // all warps done reading previous tiles
        // store staged regs -> smem (round to tf32 here)
        #pragma unroll
        for (int j = 0; j < 2; j++) {
            float4 v;
            v.x = to_tf32(aS[j].x); v.y = to_tf32(aS[j].y);
            v.z = to_tf32(aS[j].z); v.w = to_tf32(aS[j].w);
            *(float4*)&As[arow[j]][kq[j]] = v;
        }
        #pragma unroll
        for (int j = 0; j < 5; j++) {
            float4 v;
            v.x = to_tf32(wS[j].x); v.y = to_tf32(wS[j].y);
            v.z = to_tf32(wS[j].z); v.w = to_tf32(wS[j].w);
            *(float4*)&Ws[wrow[j]][wc4[j]] = v;
        }
        __syncthreads();

        // issue next-iter gmem loads (latency hidden behind MMA phase)
        if (kt + 32 < DD) {
            const int kn = kt + 32;
            #pragma unroll
            for (int j = 0; j < 2; j++) {
                float4 xv = *(const float4*)(xp[j] + kn + kq[j]);
                float4 pv = *(const float4*)(pp[j] + kn + kq[j]);
                float4 tv = *(const float4*)(tmx + kn + kq[j]);
                aS[j].x = xv.x + (pv.x - xv.x) * tv.x;
                aS[j].y = xv.y + (pv.y - xv.y) * tv.y;
                aS[j].z = xv.z + (pv.z - xv.z) * tv.z;
                aS[j].w = xv.w + (pv.w - xv.w) * tv.w;
            }
            #pragma unroll
            for (int j = 0; j < 5; j++)
                wS[j] = *(const float4*)(w1 + (size_t)(kn + wrow[j]) * N1 + wc4[j]);
        }

        // MMA phase: 4 k8 sub-steps
        #pragma unroll
        for (int s = 0; s < 4; s++) {
            const int kk = s * 8 + (lane & 3);
            unsigned a[2][4];
            #pragma unroll
            for (int h = 0; h < 2; h++) {
                int rb = wm * 32 + h * 16 + (lane >> 2);
                a[h][0] = __float_as_uint(As[rb][kk]);
                a[h][1] = __float_as_uint(As[rb + 8][kk]);
                a[h][2] = __float_as_uint(As[rb][kk + 4]);
                a[h][3] = __float_as_uint(As[rb + 8][kk + 4]);
            }
            #pragma unroll
            for (int t = 0; t < 5; t++) {
                int nn = wn * 40 + t * 8 + (lane >> 2);
                unsigned b0 = __float_as_uint(Ws[kk][nn]);
                unsigned b1 = __float_as_uint(Ws[kk + 4][nn]);
                mma_tf32(acc[0][t], a[0], b0, b1);
                mma_tf32(acc[1][t], a[1], b0, b1);
            }
        }
    }

    // epilogue: tanh, round to tf32, store H
    #pragma unroll
    for (int h = 0; h < 2; h++) {
        const int r = m0 + wm * 32 + h * 16 + (lane >> 2);
        #pragma unroll
        for (int t = 0; t < 5; t++) {
            const int cn = wn * 40 + t * 8 + (lane & 3) * 2;
            float2 v0, v1;
            v0.x = to_tf32(tanhf(acc[h][t][0]));
            v0.y = to_tf32(tanhf(acc[h][t][1]));
            v1.x = to_tf32(tanhf(acc[h][t][2]));
            v1.y = to_tf32(tanhf(acc[h][t][3]));
            *(float2*)&g_H[(size_t)r * N1 + cn] = v0;
            *(float2*)&g_H[(size_t)(r + 8) * N1 + cn] = v1;
        }
    }
}

// ---------------------------------------------------------------------------
// Kernel 2: 5x GEMM2 (H[.,32] @ W2[32,2048]) + fused epilogue, tf32 MMA.
//   out[r][f][d] = x[r][d] + sx[r][d]*(maa_f[d] + xxx)
// Block: 64 rows x 64 d-cols. 256 threads = 8 warps (4 m16 x 2 n32).
// ---------------------------------------------------------------------------
__global__ __launch_bounds__(256) void k2_gemm2_epilogue(
    const float* __restrict__ x,
    const float* __restrict__ state,
    const float* __restrict__ w2,
    const float* __restrict__ mk,
    const float* __restrict__ mw,
    const float* __restrict__ mv,
    const float* __restrict__ mr,
    const float* __restrict__ mg,
    const int* __restrict__ ip,
    float* __restrict__ out)
{
    const int i1 = SROWS * ip[0] + 1;

    __shared__ float W2s[160][72];   // tf32 bits; pad 72: (8k+d)%32 distinct -> conflict-free

    const int tid  = threadIdx.x;
    const int lane = tid & 31;
    const int warp = tid >> 5;
    const int mw2  = warp & 3;       // m16 tile: rows r0 + mw2*16
    const int nh   = warp >> 2;      // n-half:  cols d0 + nh*32 (4 n8-tiles)
    const int d0   = blockIdx.x * 64;
    const int r0   = blockIdx.y * 64;

    // load W2 tile (160 x 64) into smem, tf32-rounded
    #pragma unroll
    for (int j = 0; j < 10; j++) {
        int idx = tid + j * 256;
        int row = idx >> 4;
        int c4  = (idx & 15) * 4;
        float4 v = *(const float4*)(w2 + (size_t)row * DD + d0 + c4);
        float4 o;
        o.x = to_tf32(v.x); o.y = to_tf32(v.y);
        o.z = to_tf32(v.z); o.w = to_tf32(v.w);
        *(float4*)&W2s[row][c4] = o;
    }
    __syncthreads();

    const int rr = r0 + mw2 * 16 + (lane >> 2);     // rows rr, rr+8
    const int cb = d0 + nh * 32 + (lane & 3) * 2;   // col base per n-tile: cb + t*8

    // preload x / sx for this thread's 16 output positions
    float2 xv[2][4], sxv[2][4];
    #pragma unroll
    for (int h = 0; h < 2; h++) {
        const int r = rr + h * 8;
        const float* xrp = x + (size_t)r * DD;
        const float* prp = (r & (SS - 1))
            ? x + (size_t)(r - 1) * DD
            : state + ((size_t)(r >> 11) * SROWS + (size_t)i1) * DD;
        #pragma unroll
        for (int t = 0; t < 4; t++) {
            const int c = cb + t * 8;
            float2 a = *(const float2*)(xrp + c);
            float2 p = *(const float2*)(prp + c);
            xv[h][t] = a;
            sxv[h][t].x = p.x - a.x;
            sxv[h][t].y = p.y - a.y;
        }
    }

    const float* Hr0 = g_H + (size_t)rr * N1;
    const float* Hr1 = Hr0 + 8 * N1;
    const float* maa[5] = {mk, mw, mv, mr, mg};

    #pragma unroll
    for (int f = 0; f < 5; f++) {
        // A fragments: H[:, f*32 .. f*32+31] (already tf32-rounded)
        unsigned a[4][4];
        #pragma unroll
        for (int s = 0; s < 4; s++) {
            const int kk = f * 32 + s * 8 + (lane & 3);
            a[s][0] = __float_as_uint(__ldg(Hr0 + kk));
            a[s][1] = __float_as_uint(__ldg(Hr1 + kk));
            a[s][2] = __float_as_uint(__ldg(Hr0 + kk + 4));
            a[s][3] = __float_as_uint(__ldg(Hr1 + kk + 4));
        }

        float acc[4][4];
        #pragma unroll
        for (int t = 0; t < 4; t++)
            #pragma unroll
            for (int q = 0; q < 4; q++) acc[t][q] = 0.f;

        #pragma unroll
        for (int t = 0; t < 4; t++) {
            const int nn = nh * 32 + t * 8 + (lane >> 2);
            #pragma unroll
            for (int s = 0; s < 4; s++) {
                const int kk = f * 32 + s * 8 + (lane & 3);
                unsigned b0 = __float_as_uint(W2s[kk][nn]);
                unsigned b1 = __float_as_uint(W2s[kk + 4][nn]);
                mma_tf32(acc[t], a[s], b0, b1);
            }
        }

        // fused epilogue + store
        const float* mp = maa[f];
        float* ob0 = out + ((size_t)rr * 5 + f) * DD;
        float* ob1 = out + ((size_t)(rr + 8) * 5 + f) * DD;
        #pragma unroll
        for (int t = 0; t < 4; t++) {
            const int c = cb + t * 8;
            float2 m = *(const float2*)(mp + c);
            float2 o0, o1;
            o0.x = fmaf(sxv[0][t].x, m.x + acc[t][0], xv[0][t].x);
            o0.y = fmaf(sxv[0][t].y, m.y + acc[t][1], xv[0][t].y);
            o1.x = fmaf(sxv[1][t].x, m.x + acc[t][2], xv[1][t].x);
            o1.y = fmaf(sxv[1][t].y, m.y + acc[t][3], xv[1][t].y);
            *(float2*)(ob0 + c) = o0;
            *(float2*)(ob1 + c) = o1;
        }
    }
}

// ---------------------------------------------------------------------------
// Kernel 3: new_state = state with row i1 <- x[:, S-1]
// ---------------------------------------------------------------------------
__global__ __launch_bounds__(256) void k3_state(
    const float* __restrict__ x,
    const float* __restrict__ state,
    const int* __restrict__ ip,
    float* __restrict__ out_state)
{
    const int i1 = SROWS * ip[0] + 1;
    int idx = blockIdx.x * blockDim.x + threadIdx.x;
    const int total = BB * SROWS * DD;
    if (idx >= total) return;
    int d    = idx & (DD - 1);
    int rowg = idx >> 11;          // b*66 + row
    int row  = rowg % SROWS;
    int b    = rowg / SROWS;
    float v = (row == i1)
        ? x[((size_t)b * SS + (SS - 1)) * DD + d]
        : state[idx];
    out_state[idx] = v;
}

// ---------------------------------------------------------------------------
extern "C" void kernel_launch(void* const* d_in, const int* in_sizes, int n_in,
                              void* d_out, int out_size)
{
    const float* x     = (const float*)d_in[0];
    const float* state = (const float*)d_in[1];
    const float* tmx   = (const float*)d_in[2];
    const float* w1    = (const float*)d_in[3];
    const float* w2    = (const float*)d_in[4];
    const float* mk    = (const float*)d_in[5];
    const float* mw    = (const float*)d_in[6];
    const float* mv    = (const float*)d_in[7];
    const float* mr    = (const float*)d_in[8];
    const float* mg    = (const float*)d_in[9];
    const int*   ip    = (const int*)d_in[10];

    float* out = (float*)d_out;

    k1_mix_gemm1<<<MT / 64, 256>>>(x, state, tmx, w1, ip);

    dim3 g2(DD / 64, MT / 64);
    k2_gemm2_epilogue<<<g2, 256>>>(x, state, w2, mk, mw, mv, mr, mg, ip, out);

    const int stotal = BB * SROWS * DD;
    k3_state<<<(stotal + 255) / 256, 256>>>(x, state, ip, out + OUT_X_ELEMS);
}

// round 5
// speedup vs baseline: 3.0030x; 1.3757x over previous
#include <cuda_runtime.h>
#include <cstdint>

// Problem constants (fixed by the reference)
#define BB 4
#define SS 2048
#define DD 2048
#define N1 160                 // LoRA rank total (5 modes x 32)
#define NP 80                  // N1/2 bf16 pairs
#define MT (BB * SS)           // 8192 rows (tokens)
#define SROWS 66               // (2 + HEAD_SIZE) state rows per batch
#define OUT_X_ELEMS ((size_t)MT * 5 * DD)

// Scratch: H transposed, pair-major: g_H2T[kpair][row], kpair = 0..79
// H2T[kp*MT + r] packs bf16(H[r][2kp]) | bf16(H[r][2kp+1])<<16
__device__ unsigned g_H2T[(size_t)NP * MT];

// ---------------------------------------------------------------------------
// helpers
// ---------------------------------------------------------------------------
__device__ __forceinline__ unsigned pack_bf16(float lo, float hi) {
    unsigned r;
    asm("cvt.rn.bf16x2.f32 %0, %1, %2;" : "=r"(r) : "f"(hi), "f"(lo));
    return r;
}

__device__ __forceinline__ float tanh_fast(float x) {
    float r;
    asm("tanh.approx.f32 %0, %1;" : "=f"(r) : "f"(x));
    return r;
}

__device__ __forceinline__ void mma_bf16(float c[4], const unsigned a[4],
                                         unsigned b0, unsigned b1) {
    asm volatile(
        "mma.sync.aligned.m16n8k16.row.col.f32.bf16.bf16.f32 "
        "{%0,%1,%2,%3}, {%4,%5,%6,%7}, {%8,%9}, {%0,%1,%2,%3};"
        : "+f"(c[0]), "+f"(c[1]), "+f"(c[2]), "+f"(c[3])
        : "r"(a[0]), "r"(a[1]), "r"(a[2]), "r"(a[3]), "r"(b0), "r"(b1));
}

// ---------------------------------------------------------------------------
// Kernel 1: token-shift mix + GEMM1 (8192x2048 @ 2048x160) + tanh, bf16 MMA.
// Block: M=64, N=160, BK=32. 256 threads = 8 warps, warp-tile m32 x n40.
// Packed bf16x2 operands: 1 LDS.b32 per fragment register.
// ---------------------------------------------------------------------------
__global__ __launch_bounds__(256) void k1_mix_gemm1(
    const float* __restrict__ x,
    const float* __restrict__ state,
    const float* __restrict__ tmx,
    const float* __restrict__ w1,
    const int* __restrict__ ip)
{
    const int i1 = SROWS * ip[0] + 1;

    __shared__ unsigned As[64][20];   // [m][kpair], pad 20 -> (20r+kp)%32 all distinct
    __shared__ unsigned Ws[16][168];  // [kpair][n], pad 168 -> (8kp+n)%32 all distinct

    const int tid  = threadIdx.x;
    const int lane = tid & 31;
    const int warp = tid >> 5;
    const int wm   = warp & 1;        // m-super: rows wm*32
    const int wn   = warp >> 1;       // n-group: cols wn*40 (5 n8-tiles)
    const int m0   = blockIdx.x * 64;

    // ---- A-loader: thread -> row tid>>2, k-span (tid&3)*8 (8 floats = 4 pairs)
    const int arow = tid >> 2;
    const int ak0  = (tid & 3) * 8;
    const int akp0 = (tid & 3) * 4;
    {
        // nothing
    }
    const int r_l = m0 + arow;
    const float* xrow = x + (size_t)r_l * DD;
    const float* prow = (r_l & (SS - 1))
        ? x + (size_t)(r_l - 1) * DD
        : state + ((size_t)(r_l >> 11) * SROWS + (size_t)i1) * DD;

    // ---- W-loader: 640 tasks (16 kp x 40 n-quads); thread does tid, tid+256, tid+512(<640)
    int wkp[3], wn0[3];
    #pragma unroll
    for (int j = 0; j < 3; j++) {
        int t = tid + j * 256;
        wkp[j] = t / 40;
        wn0[j] = (t % 40) * 4;
    }
    const bool w3 = (tid < 128);

    // staged registers
    float aS[8];
    float4 wU[3], wV[3];

    // prologue: stage kt = 0
    {
        float4 xa = *(const float4*)(xrow + ak0);
        float4 xb = *(const float4*)(xrow + ak0 + 4);
        float4 pa = *(const float4*)(prow + ak0);
        float4 pb = *(const float4*)(prow + ak0 + 4);
        float4 ta = *(const float4*)(tmx + ak0);
        float4 tb = *(const float4*)(tmx + ak0 + 4);
        aS[0] = xa.x + (pa.x - xa.x) * ta.x;  aS[1] = xa.y + (pa.y - xa.y) * ta.y;
        aS[2] = xa.z + (pa.z - xa.z) * ta.z;  aS[3] = xa.w + (pa.w - xa.w) * ta.w;
        aS[4] = xb.x + (pb.x - xb.x) * tb.x;  aS[5] = xb.y + (pb.y - xb.y) * tb.y;
        aS[6] = xb.z + (pb.z - xb.z) * tb.z;  aS[7] = xb.w + (pb.w - xb.w) * tb.w;
        #pragma unroll
        for (int j = 0; j < 3; j++) {
            if (j < 2 || w3) {
                wU[j] = *(const float4*)(w1 + (size_t)(2 * wkp[j]) * N1 + wn0[j]);
                wV[j] = *(const float4*)(w1 + (size_t)(2 * wkp[j] + 1) * N1 + wn0[j]);
            }
        }
    }

    float acc[2][5][4];
    #pragma unroll
    for (int h = 0; h < 2; h++)
        #pragma unroll
        for (int t = 0; t < 5; t++)
            #pragma unroll
            for (int q = 0; q < 4; q++) acc[h][t][q] = 0.f;

    for (int kt = 0; kt < DD; kt += 32) {
        __syncthreads();
        // store staged -> smem (pack bf16 pairs)
        {
            uint4 av;
            av.x = pack_bf16(aS[0], aS[1]);
            av.y = pack_bf16(aS[2], aS[3]);
            av.z = pack_bf16(aS[4], aS[5]);
            av.w = pack_bf16(aS[6], aS[7]);
            *(uint4*)&As[arow][akp0] = av;
            #pragma unroll
            for (int j = 0; j < 3; j++) {
                if (j < 2 || w3) {
                    uint4 wvp;
                    wvp.x = pack_bf16(wU[j].x, wV[j].x);
                    wvp.y = pack_bf16(wU[j].y, wV[j].y);
                    wvp.z = pack_bf16(wU[j].z, wV[j].z);
                    wvp.w = pack_bf16(wU[j].w, wV[j].w);
                    *(uint4*)&Ws[wkp[j]][wn0[j]] = wvp;
                }
            }
        }
        __syncthreads();

        // prefetch next tile (hidden behind MMAs)
        if (kt + 32 < DD) {
            const int kn = kt + 32;
            float4 xa = *(const float4*)(xrow + kn + ak0);
            float4 xb = *(const float4*)(xrow + kn + ak0 + 4);
            float4 pa = *(const float4*)(prow + kn + ak0);
            float4 pb = *(const float4*)(prow + kn + ak0 + 4);
            float4 ta = *(const float4*)(tmx + kn + ak0);
            float4 tb = *(const float4*)(tmx + kn + ak0 + 4);
            aS[0] = xa.x + (pa.x - xa.x) * ta.x;  aS[1] = xa.y + (pa.y - xa.y) * ta.y;
            aS[2] = xa.z + (pa.z - xa.z) * ta.z;  aS[3] = xa.w + (pa.w - xa.w) * ta.w;
            aS[4] = xb.x + (pb.x - xb.x) * tb.x;  aS[5] = xb.y + (pb.y - xb.y) * tb.y;
            aS[6] = xb.z + (pb.z - xb.z) * tb.z;  aS[7] = xb.w + (pb.w - xb.w) * tb.w;
            #pragma unroll
            for (int j = 0; j < 3; j++) {
                if (j < 2 || w3) {
                    wU[j] = *(const float4*)(w1 + (size_t)(kn + 2 * wkp[j]) * N1 + wn0[j]);
                    wV[j] = *(const float4*)(w1 + (size_t)(kn + 2 * wkp[j] + 1) * N1 + wn0[j]);
                }
            }
        }

        // MMA phase: 2 k16 steps
        #pragma unroll
        for (int s = 0; s < 2; s++) {
            const int kpb = s * 8 + (lane & 3);
            unsigned a[2][4];
            #pragma unroll
            for (int h = 0; h < 2; h++) {
                const int rb = wm * 32 + h * 16 + (lane >> 2);
                a[h][0] = As[rb][kpb];
                a[h][1] = As[rb + 8][kpb];
                a[h][2] = As[rb][kpb + 4];
                a[h][3] = As[rb + 8][kpb + 4];
            }
            #pragma unroll
            for (int t = 0; t < 5; t++) {
                const int nn = wn * 40 + t * 8 + (lane >> 2);
                unsigned b0 = Ws[kpb][nn];
                unsigned b1 = Ws[kpb + 4][nn];
                mma_bf16(acc[0][t], a[0], b0, b1);
                mma_bf16(acc[1][t], a[1], b0, b1);
            }
        }
    }

    // epilogue: tanh, pack bf16 pairs, store pair-major transposed H
    #pragma unroll
    for (int h = 0; h < 2; h++) {
        const int r = m0 + wm * 32 + h * 16 + (lane >> 2);
        #pragma unroll
        for (int t = 0; t < 5; t++) {
            const int pidx = wn * 20 + t * 4 + (lane & 3);
            g_H2T[(size_t)pidx * MT + r] =
                pack_bf16(tanh_fast(acc[h][t][0]), tanh_fast(acc[h][t][1]));
            g_H2T[(size_t)pidx * MT + r + 8] =
                pack_bf16(tanh_fast(acc[h][t][2]), tanh_fast(acc[h][t][3]));
        }
    }
}

// ---------------------------------------------------------------------------
// Kernel 2: 5x GEMM2 (H[.,32] @ W2[32,2048]) + fused epilogue, bf16 MMA.
// Block: r-tile 128 x d-tile 64. 512 threads = 16 warps (8 m16 x 2 n32).
// ---------------------------------------------------------------------------
__global__ __launch_bounds__(512) void k2_gemm2_epilogue(
    const float* __restrict__ x,
    const float* __restrict__ state,
    const float* __restrict__ w2,
    const float* __restrict__ mk,
    const float* __restrict__ mw,
    const float* __restrict__ mv,
    const float* __restrict__ mr,
    const float* __restrict__ mg,
    const int* __restrict__ ip,
    float* __restrict__ out)
{
    const int i1 = SROWS * ip[0] + 1;

    __shared__ unsigned W2s[80][72];  // [kpair][d-local], pad 72 -> conflict-free

    const int tid  = threadIdx.x;
    const int lane = tid & 31;
    const int warp = tid >> 5;
    const int wm2  = warp & 7;        // rows r0 + wm2*16
    const int nh   = warp >> 3;       // cols d0 + nh*32 (4 n8-tiles)
    const int d0   = blockIdx.x * 64;
    const int r0   = blockIdx.y * 128;

    // load W2 tile (160 x 64 fp32 -> 80 x 64 bf16x2): 1280 quad-tasks over 512 threads
    #pragma unroll
    for (int j = 0; j < 3; j++) {
        int task = tid + j * 512;
        if (j < 2 || tid < 256) {
            int kp = task >> 4;
            int n0 = (task & 15) * 4;
            float4 u = *(const float4*)(w2 + (size_t)(2 * kp) * DD + d0 + n0);
            float4 v = *(const float4*)(w2 + (size_t)(2 * kp + 1) * DD + d0 + n0);
            uint4 pk;
            pk.x = pack_bf16(u.x, v.x);
            pk.y = pack_bf16(u.y, v.y);
            pk.z = pack_bf16(u.z, v.z);
            pk.w = pack_bf16(u.w, v.w);
            *(uint4*)&W2s[kp][n0] = pk;
        }
    }
    __syncthreads();

    const int rr = r0 + wm2 * 16 + (lane >> 2);     // rows rr, rr+8
    const int cb = d0 + nh * 32 + (lane & 3) * 2;   // col base: cb + t*8

    // preload x / sx for this thread's 2 rows x 4 col-pairs
    float2 xv[2][4], sxv[2][4];
    #pragma unroll
    for (int h = 0; h < 2; h++) {
        const int r = rr + h * 8;
        const float* xrp = x + (size_t)r * DD;
        const float* prp = (r & (SS - 1))
            ? x + (size_t)(r - 1) * DD
            : state + ((size_t)(r >> 11) * SROWS + (size_t)i1) * DD;
        #pragma unroll
        for (int t = 0; t < 4; t++) {
            const int c = cb + t * 8;
            float2 a = *(const float2*)(xrp + c);
            float2 p = *(const float2*)(prp + c);
            xv[h][t] = a;
            sxv[h][t].x = p.x - a.x;
            sxv[h][t].y = p.y - a.y;
        }
    }

    const float* maa[5] = {mk, mw, mv, mr, mg};

    #pragma unroll
    for (int f = 0; f < 5; f++) {
        // A fragments from pair-major H2T: 32B-sector-aligned LDGs
        unsigned a[2][4];
        #pragma unroll
        for (int s = 0; s < 2; s++) {
            const int kp = f * 16 + s * 8 + (lane & 3);
            const unsigned* h0 = g_H2T + (size_t)kp * MT;
            const unsigned* h1 = g_H2T + (size_t)(kp + 4) * MT;
            a[s][0] = __ldg(h0 + rr);
            a[s][1] = __ldg(h0 + rr + 8);
            a[s][2] = __ldg(h1 + rr);
            a[s][3] = __ldg(h1 + rr + 8);
        }

        float acc[4][4];
        #pragma unroll
        for (int t = 0; t < 4; t++)
            #pragma unroll
            for (int q = 0; q < 4; q++) acc[t][q] = 0.f;

        #pragma unroll
        for (int t = 0; t < 4; t++) {
            const int nn = nh * 32 + t * 8 + (lane >> 2);
            #pragma unroll
            for (int s = 0; s < 2; s++) {
                const int kpl = f * 16 + s * 8 + (lane & 3);
                unsigned b0 = W2s[kpl][nn];
                unsigned b1 = W2s[kpl + 4][nn];
                mma_bf16(acc[t], a[s], b0, b1);
            }
        }

        // fused epilogue + store
        const float* mp = maa[f];
        float* ob0 = out + ((size_t)rr * 5 + f) * DD;
        float* ob1 = out + ((size_t)(rr + 8) * 5 + f) * DD;
        #pragma unroll
        for (int t = 0; t < 4; t++) {
            const int c = cb + t * 8;
            float2 m = *(const float2*)(mp + c);
            float2 o0, o1;
            o0.x = fmaf(sxv[0][t].x, m.x + acc[t][0], xv[0][t].x);
            o0.y = fmaf(sxv[0][t].y, m.y + acc[t][1], xv[0][t].y);
            o1.x = fmaf(sxv[1][t].x, m.x + acc[t][2], xv[1][t].x);
            o1.y = fmaf(sxv[1][t].y, m.y + acc[t][3], xv[1][t].y);
            *(float2*)(ob0 + c) = o0;
            *(float2*)(ob1 + c) = o1;
        }
    }
}

// ---------------------------------------------------------------------------
// Kernel 3: new_state = state with row i1 <- x[:, S-1]
// ---------------------------------------------------------------------------
__global__ __launch_bounds__(256) void k3_state(
    const float* __restrict__ x,
    const float* __restrict__ state,
    const int* __restrict__ ip,
    float* __restrict__ out_state)
{
    const int i1 = SROWS * ip[0] + 1;
    int idx = blockIdx.x * blockDim.x + threadIdx.x;
    const int total = BB * SROWS * DD;
    if (idx >= total) return;
    int d    = idx & (DD - 1);
    int rowg = idx >> 11;          // b*66 + row
    int row  = rowg % SROWS;
    int b    = rowg / SROWS;
    float v = (row == i1)
        ? x[((size_t)b * SS + (SS - 1)) * DD + d]
        : state[idx];
    out_state[idx] = v;
}

// ---------------------------------------------------------------------------
extern "C" void kernel_launch(void* const* d_in, const int* in_sizes, int n_in,
                              void* d_out, int out_size)
{
    const float* x     = (const float*)d_in[0];
    const float* state = (const float*)d_in[1];
    const float* tmx   = (const float*)d_in[2];
    const float* w1    = (const float*)d_in[3];
    const float* w2    = (const float*)d_in[4];
    const float* mk    = (const float*)d_in[5];
    const float* mw    = (const float*)d_in[6];
    const float* mv    = (const float*)d_in[7];
    const float* mr    = (const float*)d_in[8];
    const float* mg    = (const float*)d_in[9];
    const int*   ip    = (const int*)d_in[10];

    float* out = (float*)d_out;

    k1_mix_gemm1<<<MT / 64, 256>>>(x, state, tmx, w1, ip);

    dim3 g2(DD / 64, MT / 128);
    k2_gemm2_epilogue<<<g2, 512>>>(x, state, w2, mk, mw, mv, mr, mg, ip, out);

    const int stotal = BB * SROWS * DD;
    k3_state<<<(stotal + 255) / 256, 256>>>(x, state, ip, out + OUT_X_ELEMS);
}

// round 8
// speedup vs baseline: 3.0690x; 1.0220x over previous
#include <cuda_runtime.h>
#include <cstdint>

// Problem constants (fixed by the reference)
#define BB 4
#define SS 2048
#define DD 2048
#define N1 160                 // LoRA rank total (5 modes x 32)
#define NP 80                  // N1/2 bf16 pairs
#define MT (BB * SS)           // 8192 rows (tokens)
#define SROWS 66               // (2 + HEAD_SIZE) state rows per batch
#define OUT_X_ELEMS ((size_t)MT * 5 * DD)

// Scratch: H transposed, pair-major: g_H2T[kpair][row]
__device__ unsigned g_H2T[(size_t)NP * MT];
// Pre-packed weights (bf16x2 along K pairs)
__device__ unsigned g_W1P[(size_t)(DD / 2) * N1];   // [1024 kp][160 n]
__device__ unsigned g_W2P[(size_t)NP * DD];         // [80 kp][2048 d]

// ---------------------------------------------------------------------------
// helpers
// ---------------------------------------------------------------------------
__device__ __forceinline__ unsigned pack_bf16(float lo, float hi) {
    unsigned r;
    asm("cvt.rn.bf16x2.f32 %0, %1, %2;" : "=r"(r) : "f"(hi), "f"(lo));
    return r;
}

__device__ __forceinline__ float tanh_fast(float x) {
    float r;
    asm("tanh.approx.f32 %0, %1;" : "=f"(r) : "f"(x));
    return r;
}

__device__ __forceinline__ void mma_bf16(float c[4], const unsigned a[4],
                                         unsigned b0, unsigned b1) {
    asm volatile(
        "mma.sync.aligned.m16n8k16.row.col.f32.bf16.bf16.f32 "
        "{%0,%1,%2,%3}, {%4,%5,%6,%7}, {%8,%9}, {%0,%1,%2,%3};"
        : "+f"(c[0]), "+f"(c[1]), "+f"(c[2]), "+f"(c[3])
        : "r"(a[0]), "r"(a[1]), "r"(a[2]), "r"(a[3]), "r"(b0), "r"(b1));
}

__device__ __forceinline__ void cp16(void* smem, const void* g) {
    unsigned sa = (unsigned)__cvta_generic_to_shared(smem);
    asm volatile("cp.async.ca.shared.global [%0], [%1], 16;" :: "r"(sa), "l"(g));
}
#define CP_COMMIT() asm volatile("cp.async.commit_group;")
#define CP_WAIT0()  asm volatile("cp.async.wait_group 0;")

// ---------------------------------------------------------------------------
// Kernel 0: pack W1/W2 to bf16x2 + state update (fused independent work)
//  zone A: W1 -> g_W1P   (1024 kp x 160, 4-wide)     40960 tasks
//  zone B: W2 -> g_W2P   (80 kp x 2048, 4-wide)      40960 tasks
//  zone C: out_state = state; row i1 <- x[:,S-1]     135168 float4 tasks
// ---------------------------------------------------------------------------
#define K0_TASKS (40960 + 40960 + 135168)
__global__ __launch_bounds__(256) void k0_pack_state(
    const float* __restrict__ w1,
    const float* __restrict__ w2,
    const float* __restrict__ x,
    const float* __restrict__ state,
    const int* __restrict__ ip,
    float* __restrict__ out_state)
{
    int idx = blockIdx.x * 256 + threadIdx.x;
    if (idx < 40960) {
        int kp = idx / 40;
        int n0 = (idx - kp * 40) * 4;
        float4 u = *(const float4*)(w1 + (size_t)(2 * kp) * N1 + n0);
        float4 v = *(const float4*)(w1 + (size_t)(2 * kp + 1) * N1 + n0);
        uint4 p;
        p.x = pack_bf16(u.x, v.x); p.y = pack_bf16(u.y, v.y);
        p.z = pack_bf16(u.z, v.z); p.w = pack_bf16(u.w, v.w);
        *(uint4*)(g_W1P + (size_t)kp * N1 + n0) = p;
    } else if (idx < 81920) {
        int t = idx - 40960;
        int kp = t >> 9;
        int n0 = (t & 511) * 4;
        float4 u = *(const float4*)(w2 + (size_t)(2 * kp) * DD + n0);
        float4 v = *(const float4*)(w2 + (size_t)(2 * kp + 1) * DD + n0);
        uint4 p;
        p.x = pack_bf16(u.x, v.x); p.y = pack_bf16(u.y, v.y);
        p.z = pack_bf16(u.z, v.z); p.w = pack_bf16(u.w, v.w);
        *(uint4*)(g_W2P + (size_t)kp * DD + n0) = p;
    } else {
        const int i1 = SROWS * ip[0] + 1;
        int t = idx - 81920;                 // float4 index over BB*SROWS*DD/4
        int d4   = (t & 511) * 4;
        int rowg = t >> 9;                   // b*66 + row
        int row  = rowg % SROWS;
        int b    = rowg / SROWS;
        float4 v = (row == i1)
            ? *(const float4*)(x + ((size_t)b * SS + (SS - 1)) * DD + d4)
            : *(const float4*)(state + (size_t)rowg * DD + d4);
        *(float4*)(out_state + (size_t)rowg * DD + d4) = v;
    }
}

// ---------------------------------------------------------------------------
// Kernel 1: token-shift mix + GEMM1 (8192x2048 @ 2048x160) + tanh, bf16 MMA.
// Block: M=64, N=160, BK=32. 512 threads = 16 warps (4m x 4n).
// Double-buffered smem; W1 tiles via cp.async from packed g_W1P; A via regs.
// One __syncthreads per K-tile.
// ---------------------------------------------------------------------------
__global__ __launch_bounds__(512) void k1_mix_gemm1(
    const float* __restrict__ x,
    const float* __restrict__ state,
    const float* __restrict__ tmx,
    const int* __restrict__ ip)
{
    const int i1 = SROWS * ip[0] + 1;

    __shared__ __align__(16) unsigned As[2][64][20];   // [m][kpair] pad 20
    __shared__ __align__(16) unsigned Ws[2][16][168];  // [kpair][n] pad 168

    const int tid  = threadIdx.x;
    const int lane = tid & 31;
    const int warp = tid >> 5;
    const int wm   = warp & 3;        // m-tile: rows wm*16
    const int wn   = warp >> 2;       // n-group: cols wn*40 (5 n8-tiles)
    const int m0   = blockIdx.x * 64;

    // A-loader: each thread 4 floats (2 pairs): row tid>>3, k off (tid&7)*4
    const int arow = tid >> 3;
    const int ak0  = (tid & 7) * 4;
    const int akp0 = (tid & 7) * 2;
    const int r_l  = m0 + arow;
    const float* xrow = x + (size_t)r_l * DD;
    const float* prow = (r_l & (SS - 1))
        ? x + (size_t)(r_l - 1) * DD
        : state + ((size_t)(r_l >> 11) * SROWS + (size_t)i1) * DD;

    // W-loader: 640 16B tasks; tid does task tid, and task tid+512 if tid<128
    const int wkpA = tid / 40, wnqA = (tid - wkpA * 40) * 4;
    const int wkpB = (tid + 512) / 40, wnqB = ((tid + 512) % 40) * 4;
    const bool hasB = (tid < 128);

    float aS[4];

    // ---- prologue: tile 0 ----
    {
        const unsigned* wb = g_W1P;  // kp base 0
        cp16(&Ws[0][wkpA][wnqA], wb + (size_t)wkpA * N1 + wnqA);
        if (hasB) cp16(&Ws[0][wkpB][wnqB], wb + (size_t)wkpB * N1 + wnqB);
        CP_COMMIT();
        float4 xa = *(const float4*)(xrow + ak0);
        float4 pa = *(const float4*)(prow + ak0);
        float4 ta = *(const float4*)(tmx + ak0);
        aS[0] = xa.x + (pa.x - xa.x) * ta.x;
        aS[1] = xa.y + (pa.y - xa.y) * ta.y;
        aS[2] = xa.z + (pa.z - xa.z) * ta.z;
        aS[3] = xa.w + (pa.w - xa.w) * ta.w;
        uint2 av;
        av.x = pack_bf16(aS[0], aS[1]);
        av.y = pack_bf16(aS[2], aS[3]);
        *(uint2*)&As[0][arow][akp0] = av;
        CP_WAIT0();
        __syncthreads();
    }

    float acc[5][4];
    #pragma unroll
    for (int t = 0; t < 5; t++)
        #pragma unroll
        for (int q = 0; q < 4; q++) acc[t][q] = 0.f;

    int buf = 0;
    for (int kt = 0; kt < DD; kt += 32) {
        const int nbuf = buf ^ 1;
        const bool more = (kt + 32 < DD);

        if (more) {
            const int kn = kt + 32;
            const unsigned* wb = g_W1P + (size_t)(kn >> 1) * N1;
            cp16(&Ws[nbuf][wkpA][wnqA], wb + (size_t)wkpA * N1 + wnqA);
            if (hasB) cp16(&Ws[nbuf][wkpB][wnqB], wb + (size_t)wkpB * N1 + wnqB);
            CP_COMMIT();
            float4 xa = *(const float4*)(xrow + kn + ak0);
            float4 pa = *(const float4*)(prow + kn + ak0);
            float4 ta = *(const float4*)(tmx + kn + ak0);
            aS[0] = xa.x + (pa.x - xa.x) * ta.x;
            aS[1] = xa.y + (pa.y - xa.y) * ta.y;
            aS[2] = xa.z + (pa.z - xa.z) * ta.z;
            aS[3] = xa.w + (pa.w - xa.w) * ta.w;
        }

        // MMA phase on current buffer: 2 k16 steps
        #pragma unroll
        for (int s = 0; s < 2; s++) {
            const int kpb = s * 8 + (lane & 3);
            const int rb  = wm * 16 + (lane >> 2);
            unsigned a[4];
            a[0] = As[buf][rb][kpb];
            a[1] = As[buf][rb + 8][kpb];
            a[2] = As[buf][rb][kpb + 4];
            a[3] = As[buf][rb + 8][kpb + 4];
            #pragma unroll
            for (int t = 0; t < 5; t++) {
                const int nn = wn * 40 + t * 8 + (lane >> 2);
                unsigned b0 = Ws[buf][kpb][nn];
                unsigned b1 = Ws[buf][kpb + 4][nn];
                mma_bf16(acc[t], a, b0, b1);
            }
        }

        if (more) {
            uint2 av;
            av.x = pack_bf16(aS[0], aS[1]);
            av.y = pack_bf16(aS[2], aS[3]);
            *(uint2*)&As[nbuf][arow][akp0] = av;
        }
        CP_WAIT0();
        __syncthreads();
        buf = nbuf;
    }

    // epilogue: tanh, pack, store pair-major transposed H
    const int r = m0 + wm * 16 + (lane >> 2);
    #pragma unroll
    for (int t = 0; t < 5; t++) {
        const int pidx = wn * 20 + t * 4 + (lane & 3);
        g_H2T[(size_t)pidx * MT + r] =
            pack_bf16(tanh_fast(acc[t][0]), tanh_fast(acc[t][1]));
        g_H2T[(size_t)pidx * MT + r + 8] =
            pack_bf16(tanh_fast(acc[t][2]), tanh_fast(acc[t][3]));
    }
}

// ---------------------------------------------------------------------------
// Kernel 2: 5x GEMM2 (H[.,32] @ W2[32,2048]) + fused epilogue, bf16 MMA.
// Block: r-tile 128 x d-tile 64. 512 threads = 16 warps (8 m16 x 2 n32).
// W2 tile via cp.async from packed g_W2P; streaming output stores.
// ---------------------------------------------------------------------------
__global__ __launch_bounds__(512) void k2_gemm2_epilogue(
    const float* __restrict__ x,
    const float* __restrict__ state,
    const float* __restrict__ mk,
    const float* __restrict__ mw,
    const float* __restrict__ mv,
    const float* __restrict__ mr,
    const float* __restrict__ mg,
    const int* __restrict__ ip,
    float* __restrict__ out)
{
    const int i1 = SROWS * ip[0] + 1;

    __shared__ __align__(16) unsigned W2s[80][72];  // [kpair][d-local] pad 72

    const int tid  = threadIdx.x;
    const int lane = tid & 31;
    const int warp = tid >> 5;
    const int wm2  = warp & 7;        // rows r0 + wm2*16
    const int nh   = warp >> 3;       // cols d0 + nh*32 (4 n8-tiles)
    const int d0   = blockIdx.x * 64;
    const int r0   = blockIdx.y * 128;

    // W2 tile: 80 kp x 64 u32 = 1280 16B tasks over 512 threads (2.5 rounds)
    {
        #pragma unroll
        for (int j = 0; j < 3; j++) {
            int task = tid + j * 512;
            if (j < 2 || tid < 256) {
                int kp = task >> 4;
                int n0 = (task & 15) * 4;
                cp16(&W2s[kp][n0], g_W2P + (size_t)kp * DD + d0 + n0);
            }
        }
        CP_COMMIT();
    }

    const int rr = r0 + wm2 * 16 + (lane >> 2);     // rows rr, rr+8
    const int cb = d0 + nh * 32 + (lane & 3) * 2;   // col base: cb + t*8

    // preload x / sx (overlaps cp.async)
    float2 xv[2][4], sxv[2][4];
    #pragma unroll
    for (int h = 0; h < 2; h++) {
        const int r = rr + h * 8;
        const float* xrp = x + (size_t)r * DD;
        const float* prp = (r & (SS - 1))
            ? x + (size_t)(r - 1) * DD
            : state + ((size_t)(r >> 11) * SROWS + (size_t)i1) * DD;
        #pragma unroll
        for (int t = 0; t < 4; t++) {
            const int c = cb + t * 8;
            float2 a = *(const float2*)(xrp + c);
            float2 p = *(const float2*)(prp + c);
            xv[h][t] = a;
            sxv[h][t].x = p.x - a.x;
            sxv[h][t].y = p.y - a.y;
        }
    }

    CP_WAIT0();
    __syncthreads();

    const float* maa[5] = {mk, mw, mv, mr, mg};

    #pragma unroll
    for (int f = 0; f < 5; f++) {
        // A fragments from pair-major H2T
        unsigned a[2][4];
        #pragma unroll
        for (int s = 0; s < 2; s++) {
            const int kp = f * 16 + s * 8 + (lane & 3);
            const unsigned* h0 = g_H2T + (size_t)kp * MT;
            const unsigned* h1 = g_H2T + (size_t)(kp + 4) * MT;
            a[s][0] = __ldg(h0 + rr);
            a[s][1] = __ldg(h0 + rr + 8);
            a[s][2] = __ldg(h1 + rr);
            a[s][3] = __ldg(h1 + rr + 8);
        }

        float acc[4][4];
        #pragma unroll
        for (int t = 0; t < 4; t++)
            #pragma unroll
            for (int q = 0; q < 4; q++) acc[t][q] = 0.f;

        #pragma unroll
        for (int t = 0; t < 4; t++) {
            const int nn = nh * 32 + t * 8 + (lane >> 2);
            #pragma unroll
            for (int s = 0; s < 2; s++) {
                const int kpl = f * 16 + s * 8 + (lane & 3);
                unsigned b0 = W2s[kpl][nn];
                unsigned b1 = W2s[kpl + 4][nn];
                mma_bf16(acc[t], a[s], b0, b1);
            }
        }

        // fused epilogue + streaming stores
        const float* mp = maa[f];
        float* ob0 = out + ((size_t)rr * 5 + f) * DD;
        float* ob1 = out + ((size_t)(rr + 8) * 5 + f) * DD;
        #pragma unroll
        for (int t = 0; t < 4; t++) {
            const int c = cb + t * 8;
            float2 m = *(const float2*)(mp + c);
            float2 o0, o1;
            o0.x = fmaf(sxv[0][t].x, m.x + acc[t][0], xv[0][t].x);
            o0.y = fmaf(sxv[0][t].y, m.y + acc[t][1], xv[0][t].y);
            o1.x = fmaf(sxv[1][t].x, m.x + acc[t][2], xv[1][t].x);
            o1.y = fmaf(sxv[1][t].y, m.y + acc[t][3], xv[1][t].y);
            __stcs((float2*)(ob0 + c), o0);
            __stcs((float2*)(ob1 + c), o1);
        }
    }
}

// ---------------------------------------------------------------------------
extern "C" void kernel_launch(void* const* d_in, const int* in_sizes, int n_in,
                              void* d_out, int out_size)
{
    const float* x     = (const float*)d_in[0];
    const float* state = (const float*)d_in[1];
    const float* tmx   = (const float*)d_in[2];
    const float* w1    = (const float*)d_in[3];
    const float* w2    = (const float*)d_in[4];
    const float* mk    = (const float*)d_in[5];
    const float* mw    = (const float*)d_in[6];
    const float* mv    = (const float*)d_in[7];
    const float* mr    = (const float*)d_in[8];
    const float* mg    = (const float*)d_in[9];
    const int*   ip    = (const int*)d_in[10];

    float* out = (float*)d_out;

    k0_pack_state<<<(K0_TASKS + 255) / 256, 256>>>(w1, w2, x, state, ip,
                                                   out + OUT_X_ELEMS);

    k1_mix_gemm1<<<MT / 64, 512>>>(x, state, tmx, ip);

    dim3 g2(DD / 64, MT / 128);
    k2_gemm2_epilogue<<<g2, 512>>>(x, state, mk, mw, mv, mr, mg, ip, out);
}

// round 9
// speedup vs baseline: 3.4388x; 1.1205x over previous
#include <cuda_runtime.h>
#include <cstdint>

// Problem constants (fixed by the reference)
#define BB 4
#define SS 2048
#define DD 2048
#define N1 160                 // LoRA rank total (5 modes x 32)
#define NP 80                  // N1/2 bf16 pairs
#define MT (BB * SS)           // 8192 rows (tokens)
#define SROWS 66               // (2 + HEAD_SIZE) state rows per batch
#define NSPLIT 4               // k1 split-K factor
#define KSLICE (DD / NSPLIT)   // 512
#define OUT_X_ELEMS ((size_t)MT * 5 * DD)

// Scratch: H transposed, pair-major: g_H2T[kpair][row]
__device__ unsigned g_H2T[(size_t)NP * MT];
// Pre-packed weights (bf16x2 along K pairs)
__device__ unsigned g_W1P[(size_t)(DD / 2) * N1];   // [1024 kp][160 n]
__device__ unsigned g_W2P[(size_t)NP * DD];         // [80 kp][2048 d]
// Split-K partials for GEMM1: [split][row][160] fp32
__device__ float g_P[(size_t)NSPLIT * MT * N1];

// ---------------------------------------------------------------------------
// helpers
// ---------------------------------------------------------------------------
__device__ __forceinline__ unsigned pack_bf16(float lo, float hi) {
    unsigned r;
    asm("cvt.rn.bf16x2.f32 %0, %1, %2;" : "=r"(r) : "f"(hi), "f"(lo));
    return r;
}

__device__ __forceinline__ float tanh_fast(float x) {
    float r;
    asm("tanh.approx.f32 %0, %1;" : "=f"(r) : "f"(x));
    return r;
}

__device__ __forceinline__ void mma_bf16(float c[4], const unsigned a[4],
                                         unsigned b0, unsigned b1) {
    asm volatile(
        "mma.sync.aligned.m16n8k16.row.col.f32.bf16.bf16.f32 "
        "{%0,%1,%2,%3}, {%4,%5,%6,%7}, {%8,%9}, {%0,%1,%2,%3};"
        : "+f"(c[0]), "+f"(c[1]), "+f"(c[2]), "+f"(c[3])
        : "r"(a[0]), "r"(a[1]), "r"(a[2]), "r"(a[3]), "r"(b0), "r"(b1));
}

__device__ __forceinline__ void cp16(void* smem, const void* g) {
    unsigned sa = (unsigned)__cvta_generic_to_shared(smem);
    asm volatile("cp.async.ca.shared.global [%0], [%1], 16;" :: "r"(sa), "l"(g));
}
#define CP_COMMIT() asm volatile("cp.async.commit_group;")
#define CP_WAIT0()  asm volatile("cp.async.wait_group 0;")

// ---------------------------------------------------------------------------
// Kernel 0: pack W1/W2 to bf16x2 + state update (fused independent work)
// ---------------------------------------------------------------------------
#define K0_TASKS (40960 + 40960 + 135168)
__global__ __launch_bounds__(256) void k0_pack_state(
    const float* __restrict__ w1,
    const float* __restrict__ w2,
    const float* __restrict__ x,
    const float* __restrict__ state,
    const int* __restrict__ ip,
    float* __restrict__ out_state)
{
    int idx = blockIdx.x * 256 + threadIdx.x;
    if (idx < 40960) {
        int kp = idx / 40;
        int n0 = (idx - kp * 40) * 4;
        float4 u = *(const float4*)(w1 + (size_t)(2 * kp) * N1 + n0);
        float4 v = *(const float4*)(w1 + (size_t)(2 * kp + 1) * N1 + n0);
        uint4 p;
        p.x = pack_bf16(u.x, v.x); p.y = pack_bf16(u.y, v.y);
        p.z = pack_bf16(u.z, v.z); p.w = pack_bf16(u.w, v.w);
        *(uint4*)(g_W1P + (size_t)kp * N1 + n0) = p;
    } else if (idx < 81920) {
        int t = idx - 40960;
        int kp = t >> 9;
        int n0 = (t & 511) * 4;
        float4 u = *(const float4*)(w2 + (size_t)(2 * kp) * DD + n0);
        float4 v = *(const float4*)(w2 + (size_t)(2 * kp + 1) * DD + n0);
        uint4 p;
        p.x = pack_bf16(u.x, v.x); p.y = pack_bf16(u.y, v.y);
        p.z = pack_bf16(u.z, v.z); p.w = pack_bf16(u.w, v.w);
        *(uint4*)(g_W2P + (size_t)kp * DD + n0) = p;
    } else {
        const int i1 = SROWS * ip[0] + 1;
        int t = idx - 81920;                 // float4 index over BB*SROWS*DD/4
        int d4   = (t & 511) * 4;
        int rowg = t >> 9;                   // b*66 + row
        int row  = rowg % SROWS;
        int b    = rowg / SROWS;
        float4 v = (row == i1)
            ? *(const float4*)(x + ((size_t)b * SS + (SS - 1)) * DD + d4)
            : *(const float4*)(state + (size_t)rowg * DD + d4);
        *(float4*)(out_state + (size_t)rowg * DD + d4) = v;
    }
}

// ---------------------------------------------------------------------------
// Kernel 1: token-shift mix + GEMM1 partial (split-K x4), bf16 MMA.
// Grid (128 m-tiles, 4 k-slices), 256 threads = 8 warps (2m x 4n), warp m32.
// Double-buffered smem; W1 via cp.async from packed g_W1P.
// Writes fp32 partials to g_P[split][row][160].
// ---------------------------------------------------------------------------
__global__ __launch_bounds__(256) void k1_mix_gemm1(
    const float* __restrict__ x,
    const float* __restrict__ state,
    const float* __restrict__ tmx,
    const int* __restrict__ ip)
{
    const int i1 = SROWS * ip[0] + 1;

    __shared__ __align__(16) unsigned As[2][64][20];   // [m][kpair] pad 20
    __shared__ __align__(16) unsigned Ws[2][16][168];  // [kpair][n] pad 168

    const int tid  = threadIdx.x;
    const int lane = tid & 31;
    const int warp = tid >> 5;
    const int wm   = warp & 1;        // m-super: rows wm*32
    const int wn   = warp >> 1;       // n-group: cols wn*40 (5 n8-tiles)
    const int m0   = blockIdx.x * 64;
    const int kbeg = blockIdx.y * KSLICE;

    // A-loader: 8 floats (4 pairs) per thread: row tid>>2, k off (tid&3)*8
    const int arow = tid >> 2;
    const int ak0  = (tid & 3) * 8;
    const int akp0 = (tid & 3) * 4;
    const int r_l  = m0 + arow;
    const float* xrow = x + (size_t)r_l * DD + kbeg;
    const float* prow = ((r_l & (SS - 1))
        ? x + (size_t)(r_l - 1) * DD
        : state + ((size_t)(r_l >> 11) * SROWS + (size_t)i1) * DD) + kbeg;
    const float* trow = tmx + kbeg;

    // W-loader: 640 16B tasks; thread does tid, tid+256, (+512 if tid<128)
    const int wkpA = tid / 40,         wnqA = (tid - wkpA * 40) * 4;
    const int wkpB = (tid + 256) / 40, wnqB = ((tid + 256) % 40) * 4;
    const int wkpC = (tid + 512) / 40, wnqC = ((tid + 512) % 40) * 4;
    const bool hasC = (tid < 128);
    const unsigned* w1p = g_W1P + (size_t)(kbeg >> 1) * N1;

    float aS[8];

    // ---- prologue: tile 0 ----
    {
        cp16(&Ws[0][wkpA][wnqA], w1p + (size_t)wkpA * N1 + wnqA);
        cp16(&Ws[0][wkpB][wnqB], w1p + (size_t)wkpB * N1 + wnqB);
        if (hasC) cp16(&Ws[0][wkpC][wnqC], w1p + (size_t)wkpC * N1 + wnqC);
        CP_COMMIT();
        float4 xa = *(const float4*)(xrow + ak0);
        float4 xb = *(const float4*)(xrow + ak0 + 4);
        float4 pa = *(const float4*)(prow + ak0);
        float4 pb = *(const float4*)(prow + ak0 + 4);
        float4 ta = *(const float4*)(trow + ak0);
        float4 tb = *(const float4*)(trow + ak0 + 4);
        aS[0] = xa.x + (pa.x - xa.x) * ta.x;  aS[1] = xa.y + (pa.y - xa.y) * ta.y;
        aS[2] = xa.z + (pa.z - xa.z) * ta.z;  aS[3] = xa.w + (pa.w - xa.w) * ta.w;
        aS[4] = xb.x + (pb.x - xb.x) * tb.x;  aS[5] = xb.y + (pb.y - xb.y) * tb.y;
        aS[6] = xb.z + (pb.z - xb.z) * tb.z;  aS[7] = xb.w + (pb.w - xb.w) * tb.w;
        uint4 av;
        av.x = pack_bf16(aS[0], aS[1]); av.y = pack_bf16(aS[2], aS[3]);
        av.z = pack_bf16(aS[4], aS[5]); av.w = pack_bf16(aS[6], aS[7]);
        *(uint4*)&As[0][arow][akp0] = av;
        CP_WAIT0();
        __syncthreads();
    }

    float acc[2][5][4];
    #pragma unroll
    for (int h = 0; h < 2; h++)
        #pragma unroll
        for (int t = 0; t < 5; t++)
            #pragma unroll
            for (int q = 0; q < 4; q++) acc[h][t][q] = 0.f;

    int buf = 0;
    for (int kt = 0; kt < KSLICE; kt += 32) {
        const int nbuf = buf ^ 1;
        const bool more = (kt + 32 < KSLICE);

        if (more) {
            const int kn = kt + 32;
            const unsigned* wb = w1p + (size_t)(kn >> 1) * N1;
            cp16(&Ws[nbuf][wkpA][wnqA], wb + (size_t)wkpA * N1 + wnqA);
            cp16(&Ws[nbuf][wkpB][wnqB], wb + (size_t)wkpB * N1 + wnqB);
            if (hasC) cp16(&Ws[nbuf][wkpC][wnqC], wb + (size_t)wkpC * N1 + wnqC);
            CP_COMMIT();
            float4 xa = *(const float4*)(xrow + kn + ak0);
            float4 xb = *(const float4*)(xrow + kn + ak0 + 4);
            float4 pa = *(const float4*)(prow + kn + ak0);
            float4 pb = *(const float4*)(prow + kn + ak0 + 4);
            float4 ta = *(const float4*)(trow + kn + ak0);
            float4 tb = *(const float4*)(trow + kn + ak0 + 4);
            aS[0] = xa.x + (pa.x - xa.x) * ta.x;  aS[1] = xa.y + (pa.y - xa.y) * ta.y;
            aS[2] = xa.z + (pa.z - xa.z) * ta.z;  aS[3] = xa.w + (pa.w - xa.w) * ta.w;
            aS[4] = xb.x + (pb.x - xb.x) * tb.x;  aS[5] = xb.y + (pb.y - xb.y) * tb.y;
            aS[6] = xb.z + (pb.z - xb.z) * tb.z;  aS[7] = xb.w + (pb.w - xb.w) * tb.w;
        }

        // MMA phase: 2 k16 steps, warp-tile m32 (h=0,1) x n40
        #pragma unroll
        for (int s = 0; s < 2; s++) {
            const int kpb = s * 8 + (lane & 3);
            unsigned a[2][4];
            #pragma unroll
            for (int h = 0; h < 2; h++) {
                const int rb = wm * 32 + h * 16 + (lane >> 2);
                a[h][0] = As[buf][rb][kpb];
                a[h][1] = As[buf][rb + 8][kpb];
                a[h][2] = As[buf][rb][kpb + 4];
                a[h][3] = As[buf][rb + 8][kpb + 4];
            }
            #pragma unroll
            for (int t = 0; t < 5; t++) {
                const int nn = wn * 40 + t * 8 + (lane >> 2);
                unsigned b0 = Ws[buf][kpb][nn];
                unsigned b1 = Ws[buf][kpb + 4][nn];
                mma_bf16(acc[0][t], a[0], b0, b1);
                mma_bf16(acc[1][t], a[1], b0, b1);
            }
        }

        if (more) {
            uint4 av;
            av.x = pack_bf16(aS[0], aS[1]); av.y = pack_bf16(aS[2], aS[3]);
            av.z = pack_bf16(aS[4], aS[5]); av.w = pack_bf16(aS[6], aS[7]);
            *(uint4*)&As[nbuf][arow][akp0] = av;
        }
        CP_WAIT0();
        __syncthreads();
        buf = nbuf;
    }

    // epilogue: store fp32 partials
    float* pbase = g_P + (size_t)blockIdx.y * MT * N1;
    #pragma unroll
    for (int h = 0; h < 2; h++) {
        const int r = m0 + wm * 32 + h * 16 + (lane >> 2);
        #pragma unroll
        for (int t = 0; t < 5; t++) {
            const int nn0 = wn * 40 + t * 8 + (lane & 3) * 2;
            *(float2*)(pbase + (size_t)r * N1 + nn0) =
                make_float2(acc[h][t][0], acc[h][t][1]);
            *(float2*)(pbase + (size_t)(r + 8) * N1 + nn0) =
                make_float2(acc[h][t][2], acc[h][t][3]);
        }
    }
}

// ---------------------------------------------------------------------------
// Kernel 1r: reduce 4 split-K partials, tanh, pack bf16, store transposed H2T.
// 256 blocks x 256 threads; block handles 32 rows x 160 cols.
// ---------------------------------------------------------------------------
__global__ __launch_bounds__(256) void k1_reduce()
{
    __shared__ float S[32][162];   // pad 162 -> 2-way worst on pack reads

    const int tid = threadIdx.x;
    const int r0  = blockIdx.x * 32;

    // accumulate: 32x160 floats = 1280 float4 tasks over 256 threads (5 rounds)
    #pragma unroll
    for (int j = 0; j < 5; j++) {
        int task = tid + j * 256;
        int row = task / 40;
        int c4  = (task - row * 40) * 4;
        const size_t off = (size_t)(r0 + row) * N1 + c4;
        float4 a = *(const float4*)(g_P + off);
        float4 b = *(const float4*)(g_P + (size_t)MT * N1 + off);
        float4 c = *(const float4*)(g_P + (size_t)2 * MT * N1 + off);
        float4 d = *(const float4*)(g_P + (size_t)3 * MT * N1 + off);
        S[row][c4 + 0] = a.x + b.x + c.x + d.x;
        S[row][c4 + 1] = a.y + b.y + c.y + d.y;
        S[row][c4 + 2] = a.z + b.z + c.z + d.z;
        S[row][c4 + 3] = a.w + b.w + c.w + d.w;
    }
    __syncthreads();

    // pack phase: warp w handles cols pairs {w, w+8, ..., w+72}, lane = row
    const int cb = tid >> 5;
    const int r  = tid & 31;
    #pragma unroll
    for (int j = 0; j < 10; j++) {
        const int c = cb + j * 8;          // kpair index 0..79
        float lo = tanh_fast(S[r][2 * c]);
        float hi = tanh_fast(S[r][2 * c + 1]);
        g_H2T[(size_t)c * MT + r0 + r] = pack_bf16(lo, hi);
    }
}

// ---------------------------------------------------------------------------
// Kernel 2: 5x GEMM2 (H[.,32] @ W2[32,2048]) + fused epilogue, bf16 MMA.
// Block: r-tile 128 x d-tile 64. 512 threads = 16 warps (8 m16 x 2 n32).
// ---------------------------------------------------------------------------
__global__ __launch_bounds__(512) void k2_gemm2_epilogue(
    const float* __restrict__ x,
    const float* __restrict__ state,
    const float* __restrict__ mk,
    const float* __restrict__ mw,
    const float* __restrict__ mv,
    const float* __restrict__ mr,
    const float* __restrict__ mg,
    const int* __restrict__ ip,
    float* __restrict__ out)
{
    const int i1 = SROWS * ip[0] + 1;

    __shared__ __align__(16) unsigned W2s[80][72];  // [kpair][d-local] pad 72

    const int tid  = threadIdx.x;
    const int lane = tid & 31;
    const int warp = tid >> 5;
    const int wm2  = warp & 7;        // rows r0 + wm2*16
    const int nh   = warp >> 3;       // cols d0 + nh*32 (4 n8-tiles)
    const int d0   = blockIdx.x * 64;
    const int r0   = blockIdx.y * 128;

    // W2 tile: 80 kp x 64 u32 = 1280 16B tasks over 512 threads (2.5 rounds)
    {
        #pragma unroll
        for (int j = 0; j < 3; j++) {
            int task = tid + j * 512;
            if (j < 2 || tid < 256) {
                int kp = task >> 4;
                int n0 = (task & 15) * 4;
                cp16(&W2s[kp][n0], g_W2P + (size_t)kp * DD + d0 + n0);
            }
        }
        CP_COMMIT();
    }

    const int rr = r0 + wm2 * 16 + (lane >> 2);     // rows rr, rr+8
    const int cb = d0 + nh * 32 + (lane & 3) * 2;   // col base: cb + t*8

    // preload x / sx (overlaps cp.async)
    float2 xv[2][4], sxv[2][4];
    #pragma unroll
    for (int h = 0; h < 2; h++) {
        const int r = rr + h * 8;
        const float* xrp = x + (size_t)r * DD;
        const float* prp = (r & (SS - 1))
            ? x + (size_t)(r - 1) * DD
            : state + ((size_t)(r >> 11) * SROWS + (size_t)i1) * DD;
        #pragma unroll
        for (int t = 0; t < 4; t++) {
            const int c = cb + t * 8;
            float2 a = *(const float2*)(xrp + c);
            float2 p = *(const float2*)(prp + c);
            xv[h][t] = a;
            sxv[h][t].x = p.x - a.x;
            sxv[h][t].y = p.y - a.y;
        }
    }

    CP_WAIT0();
    __syncthreads();

    const float* maa[5] = {mk, mw, mv, mr, mg};

    #pragma unroll
    for (int f = 0; f < 5; f++) {
        // A fragments from pair-major H2T
        unsigned a[2][4];
        #pragma unroll
        for (int s = 0; s < 2; s++) {
            const int kp = f * 16 + s * 8 + (lane & 3);
            const unsigned* h0 = g_H2T + (size_t)kp * MT;
            const unsigned* h1 = g_H2T + (size_t)(kp + 4) * MT;
            a[s][0] = __ldg(h0 + rr);
            a[s][1] = __ldg(h0 + rr + 8);
            a[s][2] = __ldg(h1 + rr);
            a[s][3] = __ldg(h1 + rr + 8);
        }

        float acc[4][4];
        #pragma unroll
        for (int t = 0; t < 4; t++)
            #pragma unroll
            for (int q = 0; q < 4; q++) acc[t][q] = 0.f;

        #pragma unroll
        for (int t = 0; t < 4; t++) {
            const int nn = nh * 32 + t * 8 + (lane >> 2);
            #pragma unroll
            for (int s = 0; s < 2; s++) {
                const int kpl = f * 16 + s * 8 + (lane & 3);
                unsigned b0 = W2s[kpl][nn];
                unsigned b1 = W2s[kpl + 4][nn];
                mma_bf16(acc[t], a[s], b0, b1);
            }
        }

        // fused epilogue + streaming stores
        const float* mp = maa[f];
        float* ob0 = out + ((size_t)rr * 5 + f) * DD;
        float* ob1 = out + ((size_t)(rr + 8) * 5 + f) * DD;
        #pragma unroll
        for (int t = 0; t < 4; t++) {
            const int c = cb + t * 8;
            float2 m = *(const float2*)(mp + c);
            float2 o0, o1;
            o0.x = fmaf(sxv[0][t].x, m.x + acc[t][0], xv[0][t].x);
            o0.y = fmaf(sxv[0][t].y, m.y + acc[t][1], xv[0][t].y);
            o1.x = fmaf(sxv[1][t].x, m.x + acc[t][2], xv[1][t].x);
            o1.y = fmaf(sxv[1][t].y, m.y + acc[t][3], xv[1][t].y);
            __stcs((float2*)(ob0 + c), o0);
            __stcs((float2*)(ob1 + c), o1);
        }
    }
}

// ---------------------------------------------------------------------------
extern "C" void kernel_launch(void* const* d_in, const int* in_sizes, int n_in,
                              void* d_out, int out_size)
{
    const float* x     = (const float*)d_in[0];
    const float* state = (const float*)d_in[1];
    const float* tmx   = (const float*)d_in[2];
    const float* w1    = (const float*)d_in[3];
    const float* w2    = (const float*)d_in[4];
    const float* mk    = (const float*)d_in[5];
    const float* mw    = (const float*)d_in[6];
    const float* mv    = (const float*)d_in[7];
    const float* mr    = (const float*)d_in[8];
    const float* mg    = (const float*)d_in[9];
    const int*   ip    = (const int*)d_in[10];

    float* out = (float*)d_out;

    k0_pack_state<<<(K0_TASKS + 255) / 256, 256>>>(w1, w2, x, state, ip,
                                                   out + OUT_X_ELEMS);

    dim3 g1(MT / 64, NSPLIT);
    k1_mix_gemm1<<<g1, 256>>>(x, state, tmx, ip);

    k1_reduce<<<MT / 32, 256>>>();

    dim3 g2(DD / 64, MT / 128);
    k2_gemm2_epilogue<<<g2, 512>>>(x, state, mk, mw, mv, mr, mg, ip, out);
}